// round 1
// baseline (speedup 1.0000x reference)
#include <cuda_runtime.h>

#define A_DIM 1024
#define B_DIM 16
#define DMODEL 512
#define NHEAD 8
#define HEAD_DIM 64
#define NTOK (A_DIM * B_DIM)   // 16384

// Scratch (allocation-free): 4 x 32 MB
__device__ float g_q[NTOK * DMODEL];
__device__ float g_k[NTOK * DMODEL];
__device__ float g_v[NTOK * DMODEL];
__device__ float g_attn[NTOK * DMODEL];

// ---------------------------------------------------------------------------
// GEMM: Y[M,N] = X[M,K] @ W[N,K]^T + bias[N]
// M=16384, N=512, K=512. BM=128, BN=64, BK=16, 256 threads, TM=8, TN=4.
// ---------------------------------------------------------------------------
__global__ __launch_bounds__(256) void gemm_xwT(
    const float* __restrict__ X,
    const float* __restrict__ W,
    const float* __restrict__ bias,
    float* __restrict__ Y)
{
    __shared__ float As[16][128];   // As[k][m]
    __shared__ float Bs[16][64];    // Bs[k][n]

    const int tid = threadIdx.x;
    const int tx = tid & 15;        // 0..15 -> n subtile
    const int ty = tid >> 4;        // 0..15 -> m subtile
    const int m0 = blockIdx.x * 128;
    const int n0 = blockIdx.y * 64;

    const int lr = tid >> 2;        // 0..63
    const int lc = (tid & 3) * 4;   // 0,4,8,12

    float acc[8][4];
#pragma unroll
    for (int i = 0; i < 8; i++)
#pragma unroll
        for (int j = 0; j < 4; j++) acc[i][j] = 0.0f;

    for (int k0 = 0; k0 < 512; k0 += 16) {
        // X tile: 128 rows x 16 cols (2 rows-of-64 per thread)
#pragma unroll
        for (int it = 0; it < 2; it++) {
            int r = lr + it * 64;
            float4 v = *(const float4*)&X[(size_t)(m0 + r) * 512 + k0 + lc];
            As[lc + 0][r] = v.x;
            As[lc + 1][r] = v.y;
            As[lc + 2][r] = v.z;
            As[lc + 3][r] = v.w;
        }
        // W tile: 64 rows x 16 cols
        {
            float4 v = *(const float4*)&W[(size_t)(n0 + lr) * 512 + k0 + lc];
            Bs[lc + 0][lr] = v.x;
            Bs[lc + 1][lr] = v.y;
            Bs[lc + 2][lr] = v.z;
            Bs[lc + 3][lr] = v.w;
        }
        __syncthreads();

#pragma unroll
        for (int k = 0; k < 16; k++) {
            float a8[8], b4[4];
            *(float4*)&a8[0] = *(const float4*)&As[k][ty * 8];
            *(float4*)&a8[4] = *(const float4*)&As[k][ty * 8 + 4];
            *(float4*)&b4[0] = *(const float4*)&Bs[k][tx * 4];
#pragma unroll
            for (int i = 0; i < 8; i++)
#pragma unroll
                for (int j = 0; j < 4; j++)
                    acc[i][j] += a8[i] * b4[j];
        }
        __syncthreads();
    }

    const int nn = n0 + tx * 4;
    float4 bv = *(const float4*)&bias[nn];
#pragma unroll
    for (int i = 0; i < 8; i++) {
        int m = m0 + ty * 8 + i;
        float4 r;
        r.x = acc[i][0] + bv.x;
        r.y = acc[i][1] + bv.y;
        r.z = acc[i][2] + bv.z;
        r.w = acc[i][3] + bv.w;
        *(float4*)&Y[(size_t)m * 512 + nn] = r;
    }
}

// ---------------------------------------------------------------------------
// Flash-style attention over the asset dim.
// grid = (A/128 q-tiles, B*NHEAD pairs), block = 256 threads (16x16).
// Per iteration: K/V block of 64 rows. Online softmax. bias[A,A] added.
// Q/K/V read from [t=a*16+b, n=h*64+d] layout; output written same layout.
// Dynamic smem: Qs[64][128] | Ks[64][64] | Vs[64][64] | Ps[128][64]  = 96 KB
// ---------------------------------------------------------------------------
__global__ __launch_bounds__(256) void attn_kernel(
    const float* __restrict__ Q,
    const float* __restrict__ K,
    const float* __restrict__ V,
    const float* __restrict__ rbias,
    float* __restrict__ O)
{
    extern __shared__ float sm[];
    float* Qs = sm;                  // Qs[d][m]: 64 x 128
    float* Ks = Qs + 64 * 128;       // Ks[d][n]: 64 x 64
    float* Vs = Ks + 64 * 64;        // Vs[n][d]: 64 x 64
    float* Ps = Vs + 64 * 64;        // Ps[m][n]: 128 x 64

    const int tid = threadIdx.x;
    const int tx = tid & 15;
    const int ty = tid >> 4;
    const int pair = blockIdx.y;
    const int b = pair >> 3;
    const int h = pair & 7;
    const int q0 = blockIdx.x * 128;
    const float scale = 0.125f;      // 1/sqrt(64)

    // Load Q tile (transposed into Qs[d][m])
    {
        const int f4 = (tid & 15) * 4;
        for (int r = tid >> 4; r < 128; r += 16) {
            int a = q0 + r;
            float4 v = *(const float4*)&Q[(size_t)(a * B_DIM + b) * DMODEL + h * HEAD_DIM + f4];
            Qs[(f4 + 0) * 128 + r] = v.x;
            Qs[(f4 + 1) * 128 + r] = v.y;
            Qs[(f4 + 2) * 128 + r] = v.z;
            Qs[(f4 + 3) * 128 + r] = v.w;
        }
    }

    float m_run[8], l_run[8], o_acc[8][4];
#pragma unroll
    for (int i = 0; i < 8; i++) {
        m_run[i] = -1e30f;
        l_run[i] = 0.0f;
#pragma unroll
        for (int j = 0; j < 4; j++) o_acc[i][j] = 0.0f;
    }
    __syncthreads();

    for (int kb = 0; kb < A_DIM; kb += 64) {
        // Load K (transposed) and V (natural) tiles
        {
            const int f4 = (tid & 15) * 4;
#pragma unroll
            for (int it = 0; it < 4; it++) {
                int r = (tid >> 4) + it * 16;
                int a = kb + r;
                size_t base = (size_t)(a * B_DIM + b) * DMODEL + h * HEAD_DIM + f4;
                float4 kv = *(const float4*)&K[base];
                Ks[(f4 + 0) * 64 + r] = kv.x;
                Ks[(f4 + 1) * 64 + r] = kv.y;
                Ks[(f4 + 2) * 64 + r] = kv.z;
                Ks[(f4 + 3) * 64 + r] = kv.w;
                float4 vv = *(const float4*)&V[base];
                *(float4*)&Vs[r * 64 + f4] = vv;
            }
        }
        __syncthreads();

        // S = Q @ K^T  (per-thread 8x4)
        float s[8][4];
#pragma unroll
        for (int i = 0; i < 8; i++)
#pragma unroll
            for (int j = 0; j < 4; j++) s[i][j] = 0.0f;

#pragma unroll
        for (int d = 0; d < 64; d++) {
            float a8[8], b4[4];
            *(float4*)&a8[0] = *(const float4*)&Qs[d * 128 + ty * 8];
            *(float4*)&a8[4] = *(const float4*)&Qs[d * 128 + ty * 8 + 4];
            *(float4*)&b4[0] = *(const float4*)&Ks[d * 64 + tx * 4];
#pragma unroll
            for (int i = 0; i < 8; i++)
#pragma unroll
                for (int j = 0; j < 4; j++)
                    s[i][j] += a8[i] * b4[j];
        }

        // scale + relation bias
#pragma unroll
        for (int i = 0; i < 8; i++) {
            int aq = q0 + ty * 8 + i;
            float4 bv = *(const float4*)&rbias[(size_t)aq * A_DIM + kb + tx * 4];
            s[i][0] = s[i][0] * scale + bv.x;
            s[i][1] = s[i][1] * scale + bv.y;
            s[i][2] = s[i][2] * scale + bv.z;
            s[i][3] = s[i][3] * scale + bv.w;
        }

        // Online softmax: row stats across the 16-lane tx group
#pragma unroll
        for (int i = 0; i < 8; i++) {
            float mx = fmaxf(fmaxf(s[i][0], s[i][1]), fmaxf(s[i][2], s[i][3]));
#pragma unroll
            for (int off = 8; off > 0; off >>= 1)
                mx = fmaxf(mx, __shfl_xor_sync(0xffffffffu, mx, off));
            float mnew = fmaxf(m_run[i], mx);
            float corr = __expf(m_run[i] - mnew);
            m_run[i] = mnew;

            float rs = 0.0f;
#pragma unroll
            for (int j = 0; j < 4; j++) {
                s[i][j] = __expf(s[i][j] - mnew);
                rs += s[i][j];
            }
#pragma unroll
            for (int off = 8; off > 0; off >>= 1)
                rs += __shfl_xor_sync(0xffffffffu, rs, off);

            l_run[i] = l_run[i] * corr + rs;
#pragma unroll
            for (int j = 0; j < 4; j++) o_acc[i][j] *= corr;
        }

        // Write P tile (float4, conflict-free)
#pragma unroll
        for (int i = 0; i < 8; i++) {
            float4 pv;
            pv.x = s[i][0]; pv.y = s[i][1]; pv.z = s[i][2]; pv.w = s[i][3];
            *(float4*)&Ps[(ty * 8 + i) * 64 + tx * 4] = pv;
        }
        __syncthreads();

        // O += P @ V  (per-thread 8m x 4d)
#pragma unroll
        for (int n = 0; n < 64; n++) {
            float b4[4];
            *(float4*)&b4[0] = *(const float4*)&Vs[n * 64 + tx * 4];
            float a8[8];
#pragma unroll
            for (int i = 0; i < 8; i++)
                a8[i] = Ps[(ty * 8 + i) * 64 + n];
#pragma unroll
            for (int i = 0; i < 8; i++)
#pragma unroll
                for (int j = 0; j < 4; j++)
                    o_acc[i][j] += a8[i] * b4[j];
        }
        __syncthreads();
    }

    // Normalize and write out: attn[(a*16+b)*512 + h*64 + d]
#pragma unroll
    for (int i = 0; i < 8; i++) {
        int aq = q0 + ty * 8 + i;
        float inv = 1.0f / l_run[i];
        float4 r;
        r.x = o_acc[i][0] * inv;
        r.y = o_acc[i][1] * inv;
        r.z = o_acc[i][2] * inv;
        r.w = o_acc[i][3] * inv;
        *(float4*)&O[(size_t)(aq * B_DIM + b) * DMODEL + h * HEAD_DIM + tx * 4] = r;
    }
}

// ---------------------------------------------------------------------------

extern "C" void kernel_launch(void* const* d_in, const int* in_sizes, int n_in,
                              void* d_out, int out_size)
{
    const float* src   = (const float*)d_in[0];
    const float* rbias = (const float*)d_in[1];
    const float* Wq    = (const float*)d_in[2];
    const float* bq    = (const float*)d_in[3];
    const float* Wk    = (const float*)d_in[4];
    const float* bk    = (const float*)d_in[5];
    const float* Wv    = (const float*)d_in[6];
    const float* bv    = (const float*)d_in[7];
    const float* Wo    = (const float*)d_in[8];
    const float* bo    = (const float*)d_in[9];
    float* out = (float*)d_out;

    float *gq, *gk, *gv, *ga;
    cudaGetSymbolAddress((void**)&gq, g_q);
    cudaGetSymbolAddress((void**)&gk, g_k);
    cudaGetSymbolAddress((void**)&gv, g_v);
    cudaGetSymbolAddress((void**)&ga, g_attn);

    const size_t attn_smem = (64 * 128 + 64 * 64 + 64 * 64 + 128 * 64) * sizeof(float); // 96 KB
    cudaFuncSetAttribute(attn_kernel, cudaFuncAttributeMaxDynamicSharedMemorySize,
                         (int)attn_smem);

    dim3 ggrid(NTOK / 128, DMODEL / 64);   // 128 x 8

    gemm_xwT<<<ggrid, 256>>>(src, Wq, bq, gq);
    gemm_xwT<<<ggrid, 256>>>(src, Wk, bk, gk);
    gemm_xwT<<<ggrid, 256>>>(src, Wv, bv, gv);

    dim3 agrid(A_DIM / 128, B_DIM * NHEAD); // 8 x 128
    attn_kernel<<<agrid, 256, attn_smem>>>(gq, gk, gv, rbias, ga);

    gemm_xwT<<<ggrid, 256>>>(ga, Wo, bo, out);
}

// round 2
// speedup vs baseline: 1.4989x; 1.4989x over previous
#include <cuda_runtime.h>
#include <cstdint>

#define A_DIM 1024
#define B_DIM 16
#define DMODEL 512
#define NHEAD 8
#define HEAD_DIM 64
#define NTOK (A_DIM * B_DIM)   // 16384

// Scratch (allocation-free): 4 x 32 MB
__device__ float g_q[NTOK * DMODEL];
__device__ float g_k[NTOK * DMODEL];
__device__ float g_v[NTOK * DMODEL];
__device__ float g_attn[NTOK * DMODEL];

__device__ __forceinline__ uint32_t f2tf32(float f) {
    uint32_t r;
    asm("cvt.rna.tf32.f32 %0, %1;" : "=r"(r) : "f"(f));
    return r;
}

// ---------------------------------------------------------------------------
// TF32 tensor-core GEMM: Y[M,N] = X[M,K] @ W[N,K]^T + bias[N]
// M=16384, N=512, K=512. BM=128, BN=128, BK=32. 256 threads = 8 warps,
// warp tile 64x32 (mma m16n8k8 grid: 4m x 4n per k8 step).
// Smem XOR-swizzled: idx = r*32 + (c ^ ((r&7)<<2))  -> conflict-free
// for both float4 stores and fragment scalar loads.
// ---------------------------------------------------------------------------
__global__ __launch_bounds__(256) void gemm_tf32(
    const float* __restrict__ X,
    const float* __restrict__ W,
    const float* __restrict__ bias,
    float* __restrict__ Y)
{
    __shared__ uint32_t Xs[128 * 32];
    __shared__ uint32_t Ws[128 * 32];

    const int tid  = threadIdx.x;
    const int warp = tid >> 5;
    const int lane = tid & 31;
    const int gid  = lane >> 2;   // 0..7
    const int tig  = lane & 3;    // 0..3

    const int m0 = blockIdx.x * 128;
    const int n0 = blockIdx.y * 128;
    const int wm0 = (warp & 1) * 64;   // 2 m-warps
    const int wn0 = (warp >> 1) * 32;  // 4 n-warps

    // gmem -> smem mapping: 128 rows x 32 cols (floats), 4 float4/thread
    const int lr  = tid >> 3;         // 0..31
    const int lc4 = (tid & 7) * 4;    // 0,4,...,28

    float acc[4][4][4];
#pragma unroll
    for (int mt = 0; mt < 4; mt++)
#pragma unroll
        for (int nt = 0; nt < 4; nt++)
#pragma unroll
            for (int i = 0; i < 4; i++) acc[mt][nt][i] = 0.0f;

    for (int k0 = 0; k0 < 512; k0 += 32) {
#pragma unroll
        for (int it = 0; it < 4; it++) {
            int rr = lr + it * 32;
            uint32_t sw = (rr & 7) << 2;
            uint32_t cbase = (uint32_t)lc4 ^ sw;
            float4 xv = *(const float4*)&X[(size_t)(m0 + rr) * 512 + k0 + lc4];
            uint4 xt = { f2tf32(xv.x), f2tf32(xv.y), f2tf32(xv.z), f2tf32(xv.w) };
            *(uint4*)&Xs[rr * 32 + cbase] = xt;
            float4 wv = *(const float4*)&W[(size_t)(n0 + rr) * 512 + k0 + lc4];
            uint4 wt = { f2tf32(wv.x), f2tf32(wv.y), f2tf32(wv.z), f2tf32(wv.w) };
            *(uint4*)&Ws[rr * 32 + cbase] = wt;
        }
        __syncthreads();

#pragma unroll
        for (int kk = 0; kk < 32; kk += 8) {
            uint32_t af[4][4], bf[4][2];
#pragma unroll
            for (int mt = 0; mt < 4; mt++) {
                int ra = wm0 + mt * 16 + gid;
                uint32_t sw = (ra & 7) << 2;
                uint32_t c0 = (uint32_t)(kk + tig) ^ sw;
                uint32_t c1 = (uint32_t)(kk + tig + 4) ^ sw;
                af[mt][0] = Xs[ra * 32 + c0];
                af[mt][1] = Xs[(ra + 8) * 32 + c0];
                af[mt][2] = Xs[ra * 32 + c1];
                af[mt][3] = Xs[(ra + 8) * 32 + c1];
            }
#pragma unroll
            for (int nt = 0; nt < 4; nt++) {
                int rb = wn0 + nt * 8 + gid;
                uint32_t sw = (rb & 7) << 2;
                bf[nt][0] = Ws[rb * 32 + ((uint32_t)(kk + tig) ^ sw)];
                bf[nt][1] = Ws[rb * 32 + ((uint32_t)(kk + tig + 4) ^ sw)];
            }
#pragma unroll
            for (int mt = 0; mt < 4; mt++)
#pragma unroll
                for (int nt = 0; nt < 4; nt++) {
                    asm volatile(
                        "mma.sync.aligned.m16n8k8.row.col.f32.tf32.tf32.f32 "
                        "{%0,%1,%2,%3}, {%4,%5,%6,%7}, {%8,%9}, {%0,%1,%2,%3};"
                        : "+f"(acc[mt][nt][0]), "+f"(acc[mt][nt][1]),
                          "+f"(acc[mt][nt][2]), "+f"(acc[mt][nt][3])
                        : "r"(af[mt][0]), "r"(af[mt][1]), "r"(af[mt][2]), "r"(af[mt][3]),
                          "r"(bf[nt][0]), "r"(bf[nt][1]));
                }
        }
        __syncthreads();
    }

    // Epilogue: c0,c1 at (gid, 2tig..2tig+1), c2,c3 at (gid+8, same cols)
#pragma unroll
    for (int mt = 0; mt < 4; mt++) {
        int mr = m0 + wm0 + mt * 16 + gid;
#pragma unroll
        for (int nt = 0; nt < 4; nt++) {
            int nc = n0 + wn0 + nt * 8 + tig * 2;
            float2 b2 = *(const float2*)&bias[nc];
            float2 r0 = { acc[mt][nt][0] + b2.x, acc[mt][nt][1] + b2.y };
            *(float2*)&Y[(size_t)mr * 512 + nc] = r0;
            float2 r1 = { acc[mt][nt][2] + b2.x, acc[mt][nt][3] + b2.y };
            *(float2*)&Y[(size_t)(mr + 8) * 512 + nc] = r1;
        }
    }
}

// ---------------------------------------------------------------------------
// Flash-style attention over the asset dim (unchanged from R1).
// ---------------------------------------------------------------------------
__global__ __launch_bounds__(256) void attn_kernel(
    const float* __restrict__ Q,
    const float* __restrict__ K,
    const float* __restrict__ V,
    const float* __restrict__ rbias,
    float* __restrict__ O)
{
    extern __shared__ float sm[];
    float* Qs = sm;                  // Qs[d][m]: 64 x 128
    float* Ks = Qs + 64 * 128;       // Ks[d][n]: 64 x 64
    float* Vs = Ks + 64 * 64;        // Vs[n][d]: 64 x 64
    float* Ps = Vs + 64 * 64;        // Ps[m][n]: 128 x 64

    const int tid = threadIdx.x;
    const int tx = tid & 15;
    const int ty = tid >> 4;
    const int pair = blockIdx.y;
    const int b = pair >> 3;
    const int h = pair & 7;
    const int q0 = blockIdx.x * 128;
    const float scale = 0.125f;

    {
        const int f4 = (tid & 15) * 4;
        for (int r = tid >> 4; r < 128; r += 16) {
            int a = q0 + r;
            float4 v = *(const float4*)&Q[(size_t)(a * B_DIM + b) * DMODEL + h * HEAD_DIM + f4];
            Qs[(f4 + 0) * 128 + r] = v.x;
            Qs[(f4 + 1) * 128 + r] = v.y;
            Qs[(f4 + 2) * 128 + r] = v.z;
            Qs[(f4 + 3) * 128 + r] = v.w;
        }
    }

    float m_run[8], l_run[8], o_acc[8][4];
#pragma unroll
    for (int i = 0; i < 8; i++) {
        m_run[i] = -1e30f;
        l_run[i] = 0.0f;
#pragma unroll
        for (int j = 0; j < 4; j++) o_acc[i][j] = 0.0f;
    }
    __syncthreads();

    for (int kb = 0; kb < A_DIM; kb += 64) {
        {
            const int f4 = (tid & 15) * 4;
#pragma unroll
            for (int it = 0; it < 4; it++) {
                int r = (tid >> 4) + it * 16;
                int a = kb + r;
                size_t base = (size_t)(a * B_DIM + b) * DMODEL + h * HEAD_DIM + f4;
                float4 kv = *(const float4*)&K[base];
                Ks[(f4 + 0) * 64 + r] = kv.x;
                Ks[(f4 + 1) * 64 + r] = kv.y;
                Ks[(f4 + 2) * 64 + r] = kv.z;
                Ks[(f4 + 3) * 64 + r] = kv.w;
                float4 vv = *(const float4*)&V[base];
                *(float4*)&Vs[r * 64 + f4] = vv;
            }
        }
        __syncthreads();

        float s[8][4];
#pragma unroll
        for (int i = 0; i < 8; i++)
#pragma unroll
            for (int j = 0; j < 4; j++) s[i][j] = 0.0f;

#pragma unroll
        for (int d = 0; d < 64; d++) {
            float a8[8], b4[4];
            *(float4*)&a8[0] = *(const float4*)&Qs[d * 128 + ty * 8];
            *(float4*)&a8[4] = *(const float4*)&Qs[d * 128 + ty * 8 + 4];
            *(float4*)&b4[0] = *(const float4*)&Ks[d * 64 + tx * 4];
#pragma unroll
            for (int i = 0; i < 8; i++)
#pragma unroll
                for (int j = 0; j < 4; j++)
                    s[i][j] += a8[i] * b4[j];
        }

#pragma unroll
        for (int i = 0; i < 8; i++) {
            int aq = q0 + ty * 8 + i;
            float4 bv = *(const float4*)&rbias[(size_t)aq * A_DIM + kb + tx * 4];
            s[i][0] = s[i][0] * scale + bv.x;
            s[i][1] = s[i][1] * scale + bv.y;
            s[i][2] = s[i][2] * scale + bv.z;
            s[i][3] = s[i][3] * scale + bv.w;
        }

#pragma unroll
        for (int i = 0; i < 8; i++) {
            float mx = fmaxf(fmaxf(s[i][0], s[i][1]), fmaxf(s[i][2], s[i][3]));
#pragma unroll
            for (int off = 8; off > 0; off >>= 1)
                mx = fmaxf(mx, __shfl_xor_sync(0xffffffffu, mx, off));
            float mnew = fmaxf(m_run[i], mx);
            float corr = __expf(m_run[i] - mnew);
            m_run[i] = mnew;

            float rs = 0.0f;
#pragma unroll
            for (int j = 0; j < 4; j++) {
                s[i][j] = __expf(s[i][j] - mnew);
                rs += s[i][j];
            }
#pragma unroll
            for (int off = 8; off > 0; off >>= 1)
                rs += __shfl_xor_sync(0xffffffffu, rs, off);

            l_run[i] = l_run[i] * corr + rs;
#pragma unroll
            for (int j = 0; j < 4; j++) o_acc[i][j] *= corr;
        }

#pragma unroll
        for (int i = 0; i < 8; i++) {
            float4 pv;
            pv.x = s[i][0]; pv.y = s[i][1]; pv.z = s[i][2]; pv.w = s[i][3];
            *(float4*)&Ps[(ty * 8 + i) * 64 + tx * 4] = pv;
        }
        __syncthreads();

#pragma unroll
        for (int n = 0; n < 64; n++) {
            float b4[4];
            *(float4*)&b4[0] = *(const float4*)&Vs[n * 64 + tx * 4];
            float a8[8];
#pragma unroll
            for (int i = 0; i < 8; i++)
                a8[i] = Ps[(ty * 8 + i) * 64 + n];
#pragma unroll
            for (int i = 0; i < 8; i++)
#pragma unroll
                for (int j = 0; j < 4; j++)
                    o_acc[i][j] += a8[i] * b4[j];
        }
        __syncthreads();
    }

#pragma unroll
    for (int i = 0; i < 8; i++) {
        int aq = q0 + ty * 8 + i;
        float inv = 1.0f / l_run[i];
        float4 r;
        r.x = o_acc[i][0] * inv;
        r.y = o_acc[i][1] * inv;
        r.z = o_acc[i][2] * inv;
        r.w = o_acc[i][3] * inv;
        *(float4*)&O[(size_t)(aq * B_DIM + b) * DMODEL + h * HEAD_DIM + tx * 4] = r;
    }
}

// ---------------------------------------------------------------------------

extern "C" void kernel_launch(void* const* d_in, const int* in_sizes, int n_in,
                              void* d_out, int out_size)
{
    const float* src   = (const float*)d_in[0];
    const float* rbias = (const float*)d_in[1];
    const float* Wq    = (const float*)d_in[2];
    const float* bq    = (const float*)d_in[3];
    const float* Wk    = (const float*)d_in[4];
    const float* bk    = (const float*)d_in[5];
    const float* Wv    = (const float*)d_in[6];
    const float* bv    = (const float*)d_in[7];
    const float* Wo    = (const float*)d_in[8];
    const float* bo    = (const float*)d_in[9];
    float* out = (float*)d_out;

    float *gq, *gk, *gv, *ga;
    cudaGetSymbolAddress((void**)&gq, g_q);
    cudaGetSymbolAddress((void**)&gk, g_k);
    cudaGetSymbolAddress((void**)&gv, g_v);
    cudaGetSymbolAddress((void**)&ga, g_attn);

    const size_t attn_smem = (64 * 128 + 64 * 64 + 64 * 64 + 128 * 64) * sizeof(float); // 96 KB
    cudaFuncSetAttribute(attn_kernel, cudaFuncAttributeMaxDynamicSharedMemorySize,
                         (int)attn_smem);

    dim3 ggrid(NTOK / 128, DMODEL / 128);   // 128 x 4

    gemm_tf32<<<ggrid, 256>>>(src, Wq, bq, gq);
    gemm_tf32<<<ggrid, 256>>>(src, Wk, bk, gk);
    gemm_tf32<<<ggrid, 256>>>(src, Wv, bv, gv);

    dim3 agrid(A_DIM / 128, B_DIM * NHEAD); // 8 x 128
    attn_kernel<<<agrid, 256, attn_smem>>>(gq, gk, gv, rbias, ga);

    gemm_tf32<<<ggrid, 256>>>(ga, Wo, bo, out);
}

// round 3
// speedup vs baseline: 1.6038x; 1.0700x over previous
#include <cuda_runtime.h>
#include <cstdint>

#define A_DIM 1024
#define B_DIM 16
#define DMODEL 512
#define NHEAD 8
#define HEAD_DIM 64
#define NTOK (A_DIM * B_DIM)   // 16384

// Scratch (allocation-free): 4 x 32 MB
__device__ float g_q[NTOK * DMODEL];
__device__ float g_k[NTOK * DMODEL];
__device__ float g_v[NTOK * DMODEL];
__device__ float g_attn[NTOK * DMODEL];

__device__ __forceinline__ uint32_t f2tf32(float f) {
    uint32_t r;
    asm("cvt.rna.tf32.f32 %0, %1;" : "=r"(r) : "f"(f));
    return r;
}

__device__ __forceinline__ void split_tf32(float x, uint32_t& hi, uint32_t& lo) {
    hi = f2tf32(x);
    lo = f2tf32(x - __uint_as_float(hi));
}

__device__ __forceinline__ void mma_tf32(float* c, const uint32_t* a,
                                         uint32_t b0, uint32_t b1) {
    asm volatile(
        "mma.sync.aligned.m16n8k8.row.col.f32.tf32.tf32.f32 "
        "{%0,%1,%2,%3}, {%4,%5,%6,%7}, {%8,%9}, {%0,%1,%2,%3};"
        : "+f"(c[0]), "+f"(c[1]), "+f"(c[2]), "+f"(c[3])
        : "r"(a[0]), "r"(a[1]), "r"(a[2]), "r"(a[3]), "r"(b0), "r"(b1));
}

// ---------------------------------------------------------------------------
// TF32 tensor-core GEMM: Y[M,N] = X[M,K] @ W[N,K]^T + bias[N]  (unchanged)
// ---------------------------------------------------------------------------
__global__ __launch_bounds__(256) void gemm_tf32(
    const float* __restrict__ X,
    const float* __restrict__ W,
    const float* __restrict__ bias,
    float* __restrict__ Y)
{
    __shared__ uint32_t Xs[128 * 32];
    __shared__ uint32_t Ws[128 * 32];

    const int tid  = threadIdx.x;
    const int warp = tid >> 5;
    const int lane = tid & 31;
    const int gid  = lane >> 2;
    const int tig  = lane & 3;

    const int m0 = blockIdx.x * 128;
    const int n0 = blockIdx.y * 128;
    const int wm0 = (warp & 1) * 64;
    const int wn0 = (warp >> 1) * 32;

    const int lr  = tid >> 3;
    const int lc4 = (tid & 7) * 4;

    float acc[4][4][4];
#pragma unroll
    for (int mt = 0; mt < 4; mt++)
#pragma unroll
        for (int nt = 0; nt < 4; nt++)
#pragma unroll
            for (int i = 0; i < 4; i++) acc[mt][nt][i] = 0.0f;

    for (int k0 = 0; k0 < 512; k0 += 32) {
#pragma unroll
        for (int it = 0; it < 4; it++) {
            int rr = lr + it * 32;
            uint32_t sw = (rr & 7) << 2;
            uint32_t cbase = (uint32_t)lc4 ^ sw;
            float4 xv = *(const float4*)&X[(size_t)(m0 + rr) * 512 + k0 + lc4];
            uint4 xt = { f2tf32(xv.x), f2tf32(xv.y), f2tf32(xv.z), f2tf32(xv.w) };
            *(uint4*)&Xs[rr * 32 + cbase] = xt;
            float4 wv = *(const float4*)&W[(size_t)(n0 + rr) * 512 + k0 + lc4];
            uint4 wt = { f2tf32(wv.x), f2tf32(wv.y), f2tf32(wv.z), f2tf32(wv.w) };
            *(uint4*)&Ws[rr * 32 + cbase] = wt;
        }
        __syncthreads();

#pragma unroll
        for (int kk = 0; kk < 32; kk += 8) {
            uint32_t af[4][4], bf[4][2];
#pragma unroll
            for (int mt = 0; mt < 4; mt++) {
                int ra = wm0 + mt * 16 + gid;
                uint32_t sw = (ra & 7) << 2;
                uint32_t c0 = (uint32_t)(kk + tig) ^ sw;
                uint32_t c1 = (uint32_t)(kk + tig + 4) ^ sw;
                af[mt][0] = Xs[ra * 32 + c0];
                af[mt][1] = Xs[(ra + 8) * 32 + c0];
                af[mt][2] = Xs[ra * 32 + c1];
                af[mt][3] = Xs[(ra + 8) * 32 + c1];
            }
#pragma unroll
            for (int nt = 0; nt < 4; nt++) {
                int rb = wn0 + nt * 8 + gid;
                uint32_t sw = (rb & 7) << 2;
                bf[nt][0] = Ws[rb * 32 + ((uint32_t)(kk + tig) ^ sw)];
                bf[nt][1] = Ws[rb * 32 + ((uint32_t)(kk + tig + 4) ^ sw)];
            }
#pragma unroll
            for (int mt = 0; mt < 4; mt++)
#pragma unroll
                for (int nt = 0; nt < 4; nt++)
                    mma_tf32(acc[mt][nt], af[mt], bf[nt][0], bf[nt][1]);
        }
        __syncthreads();
    }

#pragma unroll
    for (int mt = 0; mt < 4; mt++) {
        int mr = m0 + wm0 + mt * 16 + gid;
#pragma unroll
        for (int nt = 0; nt < 4; nt++) {
            int nc = n0 + wn0 + nt * 8 + tig * 2;
            float2 b2 = *(const float2*)&bias[nc];
            float2 r0 = { acc[mt][nt][0] + b2.x, acc[mt][nt][1] + b2.y };
            *(float2*)&Y[(size_t)mr * 512 + nc] = r0;
            float2 r1 = { acc[mt][nt][2] + b2.x, acc[mt][nt][3] + b2.y };
            *(float2*)&Y[(size_t)(mr + 8) * 512 + nc] = r1;
        }
    }
}

// ---------------------------------------------------------------------------
// Tensor-core flash attention (tf32 x3 split: error ~fp32).
// grid = (A/128, B*NHEAD), block = 256 (8 warps, each owns 16 q-rows x 64 n).
// Per kv-iter of 64: S = Q K^T (3-mma split), scale+bias, online softmax,
// P split -> smem, O += P V (3-mma split).
// Smem pitch 68 words -> all mma fragment LDS are conflict-free.
// ---------------------------------------------------------------------------
#define PAD 68

__global__ __launch_bounds__(256) void attn_mma(
    const float* __restrict__ Q,
    const float* __restrict__ K,
    const float* __restrict__ V,
    const float* __restrict__ rbias,
    float* __restrict__ O)
{
    extern __shared__ uint32_t sm[];
    uint32_t* Khi  = sm;                    // 64 x PAD
    uint32_t* Klo  = Khi  + 64 * PAD;
    uint32_t* VThi = Klo  + 64 * PAD;       // [d][kv] 64 x PAD
    uint32_t* VTlo = VThi + 64 * PAD;
    uint32_t* Phi  = VTlo + 64 * PAD;       // 128 x PAD
    uint32_t* Plo  = Phi  + 128 * PAD;

    const int tid  = threadIdx.x;
    const int warp = tid >> 5;
    const int lane = tid & 31;
    const int gid  = lane >> 2;
    const int tig  = lane & 3;

    const int pair = blockIdx.y;
    const int b = pair >> 3;
    const int h = pair & 7;
    const int q0 = blockIdx.x * 128;
    const int wm = warp * 16;
    const float scale = 0.125f;

    // ---- Q fragments in registers (whole block lifetime) ----
    uint32_t qhi[8][4], qlo[8][4];
    {
        const int r0g = q0 + wm + gid;
        const int r1g = r0g + 8;
        const size_t base0 = (size_t)(r0g * B_DIM + b) * DMODEL + h * HEAD_DIM;
        const size_t base1 = (size_t)(r1g * B_DIM + b) * DMODEL + h * HEAD_DIM;
#pragma unroll
        for (int kt = 0; kt < 8; kt++) {
            int c0 = kt * 8 + tig;
            int c1 = c0 + 4;
            split_tf32(Q[base0 + c0], qhi[kt][0], qlo[kt][0]);
            split_tf32(Q[base1 + c0], qhi[kt][1], qlo[kt][1]);
            split_tf32(Q[base0 + c1], qhi[kt][2], qlo[kt][2]);
            split_tf32(Q[base1 + c1], qhi[kt][3], qlo[kt][3]);
        }
    }

    float o[8][4];
#pragma unroll
    for (int nt = 0; nt < 8; nt++)
#pragma unroll
        for (int i = 0; i < 4; i++) o[nt][i] = 0.0f;
    float m0r = -1e30f, m1r = -1e30f, l0r = 0.0f, l1r = 0.0f;

    const int f4c = (tid & 15) * 4;        // 0..60
    const int rld = tid >> 4;              // 0..15

    for (int kb = 0; kb < A_DIM; kb += 64) {
        // ---- cooperative K / V^T load + split ----
#pragma unroll
        for (int it = 0; it < 4; it++) {
            int r = rld + it * 16;
            size_t gb = (size_t)((kb + r) * B_DIM + b) * DMODEL + h * HEAD_DIM + f4c;
            float4 kv = *(const float4*)&K[gb];
            uint4 kh, kl;
            split_tf32(kv.x, kh.x, kl.x);
            split_tf32(kv.y, kh.y, kl.y);
            split_tf32(kv.z, kh.z, kl.z);
            split_tf32(kv.w, kh.w, kl.w);
            *(uint4*)&Khi[r * PAD + f4c] = kh;
            *(uint4*)&Klo[r * PAD + f4c] = kl;
            float4 vv = *(const float4*)&V[gb];
            uint32_t vh, vl;
            split_tf32(vv.x, vh, vl); VThi[(f4c + 0) * PAD + r] = vh; VTlo[(f4c + 0) * PAD + r] = vl;
            split_tf32(vv.y, vh, vl); VThi[(f4c + 1) * PAD + r] = vh; VTlo[(f4c + 1) * PAD + r] = vl;
            split_tf32(vv.z, vh, vl); VThi[(f4c + 2) * PAD + r] = vh; VTlo[(f4c + 2) * PAD + r] = vl;
            split_tf32(vv.w, vh, vl); VThi[(f4c + 3) * PAD + r] = vh; VTlo[(f4c + 3) * PAD + r] = vl;
        }
        __syncthreads();

        // ---- S = Q K^T ----
        float s[8][4];
#pragma unroll
        for (int nt = 0; nt < 8; nt++)
#pragma unroll
            for (int i = 0; i < 4; i++) s[nt][i] = 0.0f;

#pragma unroll
        for (int kt = 0; kt < 8; kt++) {
#pragma unroll
            for (int nt = 0; nt < 8; nt++) {
                int off = (nt * 8 + gid) * PAD + kt * 8 + tig;
                uint32_t bh0 = Khi[off], bh1 = Khi[off + 4];
                uint32_t bl0 = Klo[off], bl1 = Klo[off + 4];
                mma_tf32(s[nt], qhi[kt], bh0, bh1);
                mma_tf32(s[nt], qhi[kt], bl0, bl1);
                mma_tf32(s[nt], qlo[kt], bh0, bh1);
            }
        }

        // ---- scale + relation bias ----
        {
            const float* br0 = &rbias[(size_t)(q0 + wm + gid) * A_DIM + kb];
            const float* br1 = br0 + 8 * A_DIM;
#pragma unroll
            for (int nt = 0; nt < 8; nt++) {
                float2 b0 = *(const float2*)&br0[nt * 8 + 2 * tig];
                float2 b1 = *(const float2*)&br1[nt * 8 + 2 * tig];
                s[nt][0] = s[nt][0] * scale + b0.x;
                s[nt][1] = s[nt][1] * scale + b0.y;
                s[nt][2] = s[nt][2] * scale + b1.x;
                s[nt][3] = s[nt][3] * scale + b1.y;
            }
        }

        // ---- online softmax (rows gid, gid+8 of warp band) ----
        {
            float mx0 = -1e30f, mx1 = -1e30f;
#pragma unroll
            for (int nt = 0; nt < 8; nt++) {
                mx0 = fmaxf(mx0, fmaxf(s[nt][0], s[nt][1]));
                mx1 = fmaxf(mx1, fmaxf(s[nt][2], s[nt][3]));
            }
            mx0 = fmaxf(mx0, __shfl_xor_sync(0xffffffffu, mx0, 1));
            mx0 = fmaxf(mx0, __shfl_xor_sync(0xffffffffu, mx0, 2));
            mx1 = fmaxf(mx1, __shfl_xor_sync(0xffffffffu, mx1, 1));
            mx1 = fmaxf(mx1, __shfl_xor_sync(0xffffffffu, mx1, 2));

            float mn0 = fmaxf(m0r, mx0);
            float mn1 = fmaxf(m1r, mx1);
            float c0 = __expf(m0r - mn0);
            float c1 = __expf(m1r - mn1);
            m0r = mn0; m1r = mn1;

            float rs0 = 0.0f, rs1 = 0.0f;
#pragma unroll
            for (int nt = 0; nt < 8; nt++) {
                s[nt][0] = __expf(s[nt][0] - mn0);
                s[nt][1] = __expf(s[nt][1] - mn0);
                s[nt][2] = __expf(s[nt][2] - mn1);
                s[nt][3] = __expf(s[nt][3] - mn1);
                rs0 += s[nt][0] + s[nt][1];
                rs1 += s[nt][2] + s[nt][3];
            }
            rs0 += __shfl_xor_sync(0xffffffffu, rs0, 1);
            rs0 += __shfl_xor_sync(0xffffffffu, rs0, 2);
            rs1 += __shfl_xor_sync(0xffffffffu, rs1, 1);
            rs1 += __shfl_xor_sync(0xffffffffu, rs1, 2);

            l0r = l0r * c0 + rs0;
            l1r = l1r * c1 + rs1;
#pragma unroll
            for (int nt = 0; nt < 8; nt++) {
                o[nt][0] *= c0; o[nt][1] *= c0;
                o[nt][2] *= c1; o[nt][3] *= c1;
            }
        }

        // ---- P split -> smem (warp-private rows) ----
        {
            int row0 = (wm + gid) * PAD;
            int row1 = (wm + gid + 8) * PAD;
#pragma unroll
            for (int nt = 0; nt < 8; nt++) {
                int c = nt * 8 + 2 * tig;
                uint2 h2, l2;
                split_tf32(s[nt][0], h2.x, l2.x);
                split_tf32(s[nt][1], h2.y, l2.y);
                *(uint2*)&Phi[row0 + c] = h2;
                *(uint2*)&Plo[row0 + c] = l2;
                split_tf32(s[nt][2], h2.x, l2.x);
                split_tf32(s[nt][3], h2.y, l2.y);
                *(uint2*)&Phi[row1 + c] = h2;
                *(uint2*)&Plo[row1 + c] = l2;
            }
        }
        __syncwarp();

        // ---- O += P V ----
#pragma unroll
        for (int kt = 0; kt < 8; kt++) {
            int ra = (wm + gid) * PAD + kt * 8 + tig;
            int rb = ra + 8 * PAD;
            uint32_t ah[4], al[4];
            ah[0] = Phi[ra];     ah[1] = Phi[rb];
            ah[2] = Phi[ra + 4]; ah[3] = Phi[rb + 4];
            al[0] = Plo[ra];     al[1] = Plo[rb];
            al[2] = Plo[ra + 4]; al[3] = Plo[rb + 4];
#pragma unroll
            for (int nt = 0; nt < 8; nt++) {
                int off = (nt * 8 + gid) * PAD + kt * 8 + tig;
                uint32_t bh0 = VThi[off], bh1 = VThi[off + 4];
                uint32_t bl0 = VTlo[off], bl1 = VTlo[off + 4];
                mma_tf32(o[nt], ah, bh0, bh1);
                mma_tf32(o[nt], ah, bl0, bl1);
                mma_tf32(o[nt], al, bh0, bh1);
            }
        }
        __syncthreads();
    }

    // ---- normalize + write ----
    {
        float i0 = 1.0f / l0r, i1 = 1.0f / l1r;
        const int r0g = q0 + wm + gid;
        const int r1g = r0g + 8;
        size_t base0 = (size_t)(r0g * B_DIM + b) * DMODEL + h * HEAD_DIM;
        size_t base1 = (size_t)(r1g * B_DIM + b) * DMODEL + h * HEAD_DIM;
#pragma unroll
        for (int nt = 0; nt < 8; nt++) {
            int c = nt * 8 + 2 * tig;
            float2 r0 = { o[nt][0] * i0, o[nt][1] * i0 };
            float2 r1 = { o[nt][2] * i1, o[nt][3] * i1 };
            *(float2*)&O[base0 + c] = r0;
            *(float2*)&O[base1 + c] = r1;
        }
    }
}

// ---------------------------------------------------------------------------

extern "C" void kernel_launch(void* const* d_in, const int* in_sizes, int n_in,
                              void* d_out, int out_size)
{
    const float* src   = (const float*)d_in[0];
    const float* rbias = (const float*)d_in[1];
    const float* Wq    = (const float*)d_in[2];
    const float* bq    = (const float*)d_in[3];
    const float* Wk    = (const float*)d_in[4];
    const float* bk    = (const float*)d_in[5];
    const float* Wv    = (const float*)d_in[6];
    const float* bv    = (const float*)d_in[7];
    const float* Wo    = (const float*)d_in[8];
    const float* bo    = (const float*)d_in[9];
    float* out = (float*)d_out;

    float *gq, *gk, *gv, *ga;
    cudaGetSymbolAddress((void**)&gq, g_q);
    cudaGetSymbolAddress((void**)&gk, g_k);
    cudaGetSymbolAddress((void**)&gv, g_v);
    cudaGetSymbolAddress((void**)&ga, g_attn);

    const size_t attn_smem = (size_t)(4 * 64 * PAD + 2 * 128 * PAD) * sizeof(uint32_t); // 139264
    cudaFuncSetAttribute(attn_mma, cudaFuncAttributeMaxDynamicSharedMemorySize,
                         (int)attn_smem);

    dim3 ggrid(NTOK / 128, DMODEL / 128);   // 128 x 4

    gemm_tf32<<<ggrid, 256>>>(src, Wq, bq, gq);
    gemm_tf32<<<ggrid, 256>>>(src, Wk, bk, gk);
    gemm_tf32<<<ggrid, 256>>>(src, Wv, bv, gv);

    dim3 agrid(A_DIM / 128, B_DIM * NHEAD); // 8 x 128
    attn_mma<<<agrid, 256, attn_smem>>>(gq, gk, gv, rbias, ga);

    gemm_tf32<<<ggrid, 256>>>(ga, Wo, bo, out);
}

// round 4
// speedup vs baseline: 2.5893x; 1.6145x over previous
#include <cuda_runtime.h>
#include <cuda_fp16.h>
#include <cstdint>

#define A_DIM 1024
#define B_DIM 16
#define DMODEL 512
#define NHEAD 8
#define HEAD_DIM 64
#define NTOK (A_DIM * B_DIM)   // 16384

// Scratch (allocation-free): 4 x 32 MB
__device__ float g_q[NTOK * DMODEL];
__device__ float g_k[NTOK * DMODEL];
__device__ float g_v[NTOK * DMODEL];
__device__ float g_attn[NTOK * DMODEL];

__device__ __forceinline__ uint32_t f2tf32(float f) {
    uint32_t r;
    asm("cvt.rna.tf32.f32 %0, %1;" : "=r"(r) : "f"(f));
    return r;
}

__device__ __forceinline__ void mma_tf32(float* c, const uint32_t* a,
                                         uint32_t b0, uint32_t b1) {
    asm volatile(
        "mma.sync.aligned.m16n8k8.row.col.f32.tf32.tf32.f32 "
        "{%0,%1,%2,%3}, {%4,%5,%6,%7}, {%8,%9}, {%0,%1,%2,%3};"
        : "+f"(c[0]), "+f"(c[1]), "+f"(c[2]), "+f"(c[3])
        : "r"(a[0]), "r"(a[1]), "r"(a[2]), "r"(a[3]), "r"(b0), "r"(b1));
}

__device__ __forceinline__ void mma_f16(float* c, const uint32_t* a,
                                        uint32_t b0, uint32_t b1) {
    asm volatile(
        "mma.sync.aligned.m16n8k16.row.col.f32.f16.f16.f32 "
        "{%0,%1,%2,%3}, {%4,%5,%6,%7}, {%8,%9}, {%0,%1,%2,%3};"
        : "+f"(c[0]), "+f"(c[1]), "+f"(c[2]), "+f"(c[3])
        : "r"(a[0]), "r"(a[1]), "r"(a[2]), "r"(a[3]), "r"(b0), "r"(b1));
}

// fp16 2-way split of a pair of floats, packed as half2 words.
__device__ __forceinline__ void split_h2(float x, float y,
                                         uint32_t& hi, uint32_t& lo) {
    __half2 h = __floats2half2_rn(x, y);
    float rx = x - __half2float(__low2half(h));
    float ry = y - __half2float(__high2half(h));
    __half2 l = __floats2half2_rn(rx, ry);
    hi = *(uint32_t*)&h;
    lo = *(uint32_t*)&l;
}

// ---------------------------------------------------------------------------
// TF32 tensor-core GEMM: Y[M,N] = X[M,K] @ W[N,K]^T + bias[N]  (unchanged)
// ---------------------------------------------------------------------------
__global__ __launch_bounds__(256) void gemm_tf32(
    const float* __restrict__ X,
    const float* __restrict__ W,
    const float* __restrict__ bias,
    float* __restrict__ Y)
{
    __shared__ uint32_t Xs[128 * 32];
    __shared__ uint32_t Ws[128 * 32];

    const int tid  = threadIdx.x;
    const int warp = tid >> 5;
    const int lane = tid & 31;
    const int gid  = lane >> 2;
    const int tig  = lane & 3;

    const int m0 = blockIdx.x * 128;
    const int n0 = blockIdx.y * 128;
    const int wm0 = (warp & 1) * 64;
    const int wn0 = (warp >> 1) * 32;

    const int lr  = tid >> 3;
    const int lc4 = (tid & 7) * 4;

    float acc[4][4][4];
#pragma unroll
    for (int mt = 0; mt < 4; mt++)
#pragma unroll
        for (int nt = 0; nt < 4; nt++)
#pragma unroll
            for (int i = 0; i < 4; i++) acc[mt][nt][i] = 0.0f;

    for (int k0 = 0; k0 < 512; k0 += 32) {
#pragma unroll
        for (int it = 0; it < 4; it++) {
            int rr = lr + it * 32;
            uint32_t sw = (rr & 7) << 2;
            uint32_t cbase = (uint32_t)lc4 ^ sw;
            float4 xv = *(const float4*)&X[(size_t)(m0 + rr) * 512 + k0 + lc4];
            uint4 xt = { f2tf32(xv.x), f2tf32(xv.y), f2tf32(xv.z), f2tf32(xv.w) };
            *(uint4*)&Xs[rr * 32 + cbase] = xt;
            float4 wv = *(const float4*)&W[(size_t)(n0 + rr) * 512 + k0 + lc4];
            uint4 wt = { f2tf32(wv.x), f2tf32(wv.y), f2tf32(wv.z), f2tf32(wv.w) };
            *(uint4*)&Ws[rr * 32 + cbase] = wt;
        }
        __syncthreads();

#pragma unroll
        for (int kk = 0; kk < 32; kk += 8) {
            uint32_t af[4][4], bf[4][2];
#pragma unroll
            for (int mt = 0; mt < 4; mt++) {
                int ra = wm0 + mt * 16 + gid;
                uint32_t sw = (ra & 7) << 2;
                uint32_t c0 = (uint32_t)(kk + tig) ^ sw;
                uint32_t c1 = (uint32_t)(kk + tig + 4) ^ sw;
                af[mt][0] = Xs[ra * 32 + c0];
                af[mt][1] = Xs[(ra + 8) * 32 + c0];
                af[mt][2] = Xs[ra * 32 + c1];
                af[mt][3] = Xs[(ra + 8) * 32 + c1];
            }
#pragma unroll
            for (int nt = 0; nt < 4; nt++) {
                int rb = wn0 + nt * 8 + gid;
                uint32_t sw = (rb & 7) << 2;
                bf[nt][0] = Ws[rb * 32 + ((uint32_t)(kk + tig) ^ sw)];
                bf[nt][1] = Ws[rb * 32 + ((uint32_t)(kk + tig + 4) ^ sw)];
            }
#pragma unroll
            for (int mt = 0; mt < 4; mt++)
#pragma unroll
                for (int nt = 0; nt < 4; nt++)
                    mma_tf32(acc[mt][nt], af[mt], bf[nt][0], bf[nt][1]);
        }
        __syncthreads();
    }

#pragma unroll
    for (int mt = 0; mt < 4; mt++) {
        int mr = m0 + wm0 + mt * 16 + gid;
#pragma unroll
        for (int nt = 0; nt < 4; nt++) {
            int nc = n0 + wn0 + nt * 8 + tig * 2;
            float2 b2 = *(const float2*)&bias[nc];
            float2 r0 = { acc[mt][nt][0] + b2.x, acc[mt][nt][1] + b2.y };
            *(float2*)&Y[(size_t)mr * 512 + nc] = r0;
            float2 r1 = { acc[mt][nt][2] + b2.x, acc[mt][nt][3] + b2.y };
            *(float2*)&Y[(size_t)(mr + 8) * 512 + nc] = r1;
        }
    }
}

// ---------------------------------------------------------------------------
// fp16-split tensor-core flash attention (hi/lo split => ~fp32 accuracy).
// grid = (A/128, B*NHEAD), block = 256 (8 warps x 16 q-rows).
// mma m16n8k16; P stays in registers (accum layout == A-frag layout).
// K smem: half2 pairs along d, pitch 36 words. V smem: half2 pairs along kv,
// pitch 72 words. All fragment LDS conflict-free.
// ---------------------------------------------------------------------------
#define KP 36
#define VP 72

__global__ __launch_bounds__(256, 2) void attn_mma(
    const float* __restrict__ Q,
    const float* __restrict__ K,
    const float* __restrict__ V,
    const float* __restrict__ rbias,
    float* __restrict__ O)
{
    __shared__ uint32_t Khi[64 * KP];
    __shared__ uint32_t Klo[64 * KP];
    __shared__ uint32_t Vph[32 * VP];
    __shared__ uint32_t Vpl[32 * VP];

    const int tid  = threadIdx.x;
    const int warp = tid >> 5;
    const int lane = tid & 31;
    const int gid  = lane >> 2;
    const int tig  = lane & 3;

    const int pair = blockIdx.y;
    const int b = pair >> 3;
    const int h = pair & 7;
    const int q0 = blockIdx.x * 128;
    const int wm = warp * 16;
    const float scale = 0.125f;

    // ---- Q fragments in registers (fp16 split, packed half2) ----
    uint32_t qhi[4][4], qlo[4][4];
    {
        const int r0g = q0 + wm + gid;
        const size_t base0 = (size_t)(r0g * B_DIM + b) * DMODEL + h * HEAD_DIM;
        const size_t base1 = base0 + (size_t)8 * B_DIM * DMODEL;
#pragma unroll
        for (int kt = 0; kt < 4; kt++) {
            int c0 = kt * 16 + 2 * tig;
            float2 x0 = *(const float2*)&Q[base0 + c0];
            float2 x1 = *(const float2*)&Q[base1 + c0];
            float2 x2 = *(const float2*)&Q[base0 + c0 + 8];
            float2 x3 = *(const float2*)&Q[base1 + c0 + 8];
            split_h2(x0.x, x0.y, qhi[kt][0], qlo[kt][0]);
            split_h2(x1.x, x1.y, qhi[kt][1], qlo[kt][1]);
            split_h2(x2.x, x2.y, qhi[kt][2], qlo[kt][2]);
            split_h2(x3.x, x3.y, qhi[kt][3], qlo[kt][3]);
        }
    }

    float o[8][4];
#pragma unroll
    for (int nt = 0; nt < 8; nt++)
#pragma unroll
        for (int i = 0; i < 4; i++) o[nt][i] = 0.0f;
    float m0r = -1e30f, m1r = -1e30f, l0r = 0.0f, l1r = 0.0f;

    const int f4c = (tid & 15) * 4;        // 0..60
    const int rld = tid >> 4;              // 0..15

    for (int kb = 0; kb < A_DIM; kb += 64) {
        // ---- cooperative K / V load + fp16 split ----
#pragma unroll
        for (int it = 0; it < 4; it++) {
            int r = rld + it * 16;
            size_t gb = (size_t)((kb + r) * B_DIM + b) * DMODEL + h * HEAD_DIM + f4c;
            float4 kv4 = *(const float4*)&K[gb];
            uint2 kh, kl;
            split_h2(kv4.x, kv4.y, kh.x, kl.x);
            split_h2(kv4.z, kv4.w, kh.y, kl.y);
            *(uint2*)&Khi[r * KP + (f4c >> 1)] = kh;
            *(uint2*)&Klo[r * KP + (f4c >> 1)] = kl;

            float4 vv = *(const float4*)&V[gb];
            int hidx = ((r >> 1) * VP + f4c) * 2 + (r & 1);
            float vf[4] = { vv.x, vv.y, vv.z, vv.w };
#pragma unroll
            for (int j = 0; j < 4; j++) {
                __half hv = __float2half_rn(vf[j]);
                __half lv = __float2half_rn(vf[j] - __half2float(hv));
                ((__half*)Vph)[hidx + 2 * j] = hv;
                ((__half*)Vpl)[hidx + 2 * j] = lv;
            }
        }
        __syncthreads();

        // ---- S = Q K^T ----
        float s[8][4];
#pragma unroll
        for (int nt = 0; nt < 8; nt++)
#pragma unroll
            for (int i = 0; i < 4; i++) s[nt][i] = 0.0f;

#pragma unroll
        for (int kt = 0; kt < 4; kt++) {
#pragma unroll
            for (int nt = 0; nt < 8; nt++) {
                int wb = (nt * 8 + gid) * KP + kt * 8 + tig;
                uint32_t bh0 = Khi[wb], bh1 = Khi[wb + 4];
                uint32_t bl0 = Klo[wb], bl1 = Klo[wb + 4];
                mma_f16(s[nt], qhi[kt], bh0, bh1);
                mma_f16(s[nt], qlo[kt], bh0, bh1);
                mma_f16(s[nt], qhi[kt], bl0, bl1);
            }
        }

        // ---- scale + relation bias ----
        {
            const float* br0 = &rbias[(size_t)(q0 + wm + gid) * A_DIM + kb];
            const float* br1 = br0 + 8 * A_DIM;
#pragma unroll
            for (int nt = 0; nt < 8; nt++) {
                float2 b0 = *(const float2*)&br0[nt * 8 + 2 * tig];
                float2 b1 = *(const float2*)&br1[nt * 8 + 2 * tig];
                s[nt][0] = s[nt][0] * scale + b0.x;
                s[nt][1] = s[nt][1] * scale + b0.y;
                s[nt][2] = s[nt][2] * scale + b1.x;
                s[nt][3] = s[nt][3] * scale + b1.y;
            }
        }

        // ---- online softmax (rows gid, gid+8) ----
        {
            float mx0 = -1e30f, mx1 = -1e30f;
#pragma unroll
            for (int nt = 0; nt < 8; nt++) {
                mx0 = fmaxf(mx0, fmaxf(s[nt][0], s[nt][1]));
                mx1 = fmaxf(mx1, fmaxf(s[nt][2], s[nt][3]));
            }
            mx0 = fmaxf(mx0, __shfl_xor_sync(0xffffffffu, mx0, 1));
            mx0 = fmaxf(mx0, __shfl_xor_sync(0xffffffffu, mx0, 2));
            mx1 = fmaxf(mx1, __shfl_xor_sync(0xffffffffu, mx1, 1));
            mx1 = fmaxf(mx1, __shfl_xor_sync(0xffffffffu, mx1, 2));

            float mn0 = fmaxf(m0r, mx0);
            float mn1 = fmaxf(m1r, mx1);
            float c0 = __expf(m0r - mn0);
            float c1 = __expf(m1r - mn1);
            m0r = mn0; m1r = mn1;

            float rs0 = 0.0f, rs1 = 0.0f;
#pragma unroll
            for (int nt = 0; nt < 8; nt++) {
                s[nt][0] = __expf(s[nt][0] - mn0);
                s[nt][1] = __expf(s[nt][1] - mn0);
                s[nt][2] = __expf(s[nt][2] - mn1);
                s[nt][3] = __expf(s[nt][3] - mn1);
                rs0 += s[nt][0] + s[nt][1];
                rs1 += s[nt][2] + s[nt][3];
            }
            rs0 += __shfl_xor_sync(0xffffffffu, rs0, 1);
            rs0 += __shfl_xor_sync(0xffffffffu, rs0, 2);
            rs1 += __shfl_xor_sync(0xffffffffu, rs1, 1);
            rs1 += __shfl_xor_sync(0xffffffffu, rs1, 2);

            l0r = l0r * c0 + rs0;
            l1r = l1r * c1 + rs1;
#pragma unroll
            for (int nt = 0; nt < 8; nt++) {
                o[nt][0] *= c0; o[nt][1] *= c0;
                o[nt][2] *= c1; o[nt][3] *= c1;
            }
        }

        // ---- O += P V  (P direct from registers) ----
#pragma unroll
        for (int j = 0; j < 4; j++) {
            uint32_t ah[4], al[4];
            split_h2(s[2*j][0],   s[2*j][1],   ah[0], al[0]);
            split_h2(s[2*j][2],   s[2*j][3],   ah[1], al[1]);
            split_h2(s[2*j+1][0], s[2*j+1][1], ah[2], al[2]);
            split_h2(s[2*j+1][2], s[2*j+1][3], ah[3], al[3]);
#pragma unroll
            for (int nt = 0; nt < 8; nt++) {
                int wb = (j * 8 + tig) * VP + nt * 8 + gid;
                uint32_t bh0 = Vph[wb], bh1 = Vph[wb + 4 * VP];
                uint32_t bl0 = Vpl[wb], bl1 = Vpl[wb + 4 * VP];
                mma_f16(o[nt], ah, bh0, bh1);
                mma_f16(o[nt], al, bh0, bh1);
                mma_f16(o[nt], ah, bl0, bl1);
            }
        }
        __syncthreads();
    }

    // ---- normalize + write ----
    {
        float i0 = 1.0f / l0r, i1 = 1.0f / l1r;
        const int r0g = q0 + wm + gid;
        size_t base0 = (size_t)(r0g * B_DIM + b) * DMODEL + h * HEAD_DIM;
        size_t base1 = base0 + (size_t)8 * B_DIM * DMODEL;
#pragma unroll
        for (int nt = 0; nt < 8; nt++) {
            int c = nt * 8 + 2 * tig;
            float2 r0 = { o[nt][0] * i0, o[nt][1] * i0 };
            float2 r1 = { o[nt][2] * i1, o[nt][3] * i1 };
            *(float2*)&O[base0 + c] = r0;
            *(float2*)&O[base1 + c] = r1;
        }
    }
}

// ---------------------------------------------------------------------------

extern "C" void kernel_launch(void* const* d_in, const int* in_sizes, int n_in,
                              void* d_out, int out_size)
{
    const float* src   = (const float*)d_in[0];
    const float* rbias = (const float*)d_in[1];
    const float* Wq    = (const float*)d_in[2];
    const float* bq    = (const float*)d_in[3];
    const float* Wk    = (const float*)d_in[4];
    const float* bk    = (const float*)d_in[5];
    const float* Wv    = (const float*)d_in[6];
    const float* bv    = (const float*)d_in[7];
    const float* Wo    = (const float*)d_in[8];
    const float* bo    = (const float*)d_in[9];
    float* out = (float*)d_out;

    float *gq, *gk, *gv, *ga;
    cudaGetSymbolAddress((void**)&gq, g_q);
    cudaGetSymbolAddress((void**)&gk, g_k);
    cudaGetSymbolAddress((void**)&gv, g_v);
    cudaGetSymbolAddress((void**)&ga, g_attn);

    dim3 ggrid(NTOK / 128, DMODEL / 128);   // 128 x 4

    gemm_tf32<<<ggrid, 256>>>(src, Wq, bq, gq);
    gemm_tf32<<<ggrid, 256>>>(src, Wk, bk, gk);
    gemm_tf32<<<ggrid, 256>>>(src, Wv, bv, gv);

    dim3 agrid(A_DIM / 128, B_DIM * NHEAD); // 8 x 128
    attn_mma<<<agrid, 256>>>(gq, gk, gv, rbias, ga);

    gemm_tf32<<<ggrid, 256>>>(ga, Wo, bo, out);
}

// round 5
// speedup vs baseline: 3.3706x; 1.3017x over previous
#include <cuda_runtime.h>
#include <cuda_fp16.h>
#include <cstdint>

#define A_DIM 1024
#define B_DIM 16
#define DMODEL 512
#define NHEAD 8
#define HEAD_DIM 64
#define NTOK (A_DIM * B_DIM)   // 16384

// Scratch (allocation-free)
__device__ float g_q[NTOK * DMODEL];
__device__ float g_k[NTOK * DMODEL];
__device__ float g_v[NTOK * DMODEL];
__device__ float g_attn[NTOK * DMODEL];
__device__ float g_x32[NTOK * DMODEL];
__device__ float g_wq32[DMODEL * DMODEL];
__device__ float g_wk32[DMODEL * DMODEL];
__device__ float g_wv32[DMODEL * DMODEL];
__device__ float g_wo32[DMODEL * DMODEL];

__device__ __forceinline__ uint32_t f2tf32(float f) {
    uint32_t r;
    asm("cvt.rna.tf32.f32 %0, %1;" : "=r"(r) : "f"(f));
    return r;
}

__device__ __forceinline__ void mma_tf32(float* c, const uint32_t* a,
                                         uint32_t b0, uint32_t b1) {
    asm volatile(
        "mma.sync.aligned.m16n8k8.row.col.f32.tf32.tf32.f32 "
        "{%0,%1,%2,%3}, {%4,%5,%6,%7}, {%8,%9}, {%0,%1,%2,%3};"
        : "+f"(c[0]), "+f"(c[1]), "+f"(c[2]), "+f"(c[3])
        : "r"(a[0]), "r"(a[1]), "r"(a[2]), "r"(a[3]), "r"(b0), "r"(b1));
}

__device__ __forceinline__ void mma_f16(float* c, const uint32_t* a,
                                        uint32_t b0, uint32_t b1) {
    asm volatile(
        "mma.sync.aligned.m16n8k16.row.col.f32.f16.f16.f32 "
        "{%0,%1,%2,%3}, {%4,%5,%6,%7}, {%8,%9}, {%0,%1,%2,%3};"
        : "+f"(c[0]), "+f"(c[1]), "+f"(c[2]), "+f"(c[3])
        : "r"(a[0]), "r"(a[1]), "r"(a[2]), "r"(a[3]), "r"(b0), "r"(b1));
}

__device__ __forceinline__ uint32_t pack_h2(float x, float y) {
    __half2 h = __floats2half2_rn(x, y);
    return *(uint32_t*)&h;
}

__device__ __forceinline__ void split_h2(float x, float y,
                                         uint32_t& hi, uint32_t& lo) {
    __half2 h = __floats2half2_rn(x, y);
    float rx = x - __half2float(__low2half(h));
    float ry = y - __half2float(__high2half(h));
    __half2 l = __floats2half2_rn(rx, ry);
    hi = *(uint32_t*)&h;
    lo = *(uint32_t*)&l;
}

__device__ __forceinline__ void cp16(uint32_t dst_s, const void* src) {
    asm volatile("cp.async.cg.shared.global [%0], [%1], 16;"
                 :: "r"(dst_s), "l"(src));
}

// ---------------------------------------------------------------------------
// Pre-round src + weights to tf32 (rna) so GEMMs can cp.async raw bytes.
// ---------------------------------------------------------------------------
#define NX4 2097152   // NTOK*DMODEL/4
#define NW4 65536     // DMODEL*DMODEL/4

__global__ void tf32_round_all(
    const float4* __restrict__ src,
    const float4* __restrict__ wq, const float4* __restrict__ wk,
    const float4* __restrict__ wv, const float4* __restrict__ wo,
    float4* __restrict__ xo,
    float4* __restrict__ wqo, float4* __restrict__ wko,
    float4* __restrict__ wvo, float4* __restrict__ woo)
{
    int idx = blockIdx.x * 256 + threadIdx.x;
    if (idx >= NX4 + 4 * NW4) return;
    const float4* in; float4* out; int off;
    if (idx < NX4) { in = src; out = xo; off = idx; }
    else {
        int t = idx - NX4;
        int seg = t >> 16;
        off = t & (NW4 - 1);
        in  = seg == 0 ? wq  : seg == 1 ? wk  : seg == 2 ? wv  : wo;
        out = seg == 0 ? wqo : seg == 1 ? wko : seg == 2 ? wvo : woo;
    }
    float4 v = in[off];
    v.x = __uint_as_float(f2tf32(v.x));
    v.y = __uint_as_float(f2tf32(v.y));
    v.z = __uint_as_float(f2tf32(v.z));
    v.w = __uint_as_float(f2tf32(v.w));
    out[off] = v;
}

// ---------------------------------------------------------------------------
// Pipelined TF32 GEMM (cp.async 2-stage): Y = X @ W^T + bias.
// Inputs pre-rounded to tf32. blockIdx.z selects (W, bias, Y).
// BM=128, BN=128, BK=32; 8 warps, warp tile 64x32.
// dyn smem: 2 stages x (Xs 16KB + Ws 16KB) = 64 KB.
// ---------------------------------------------------------------------------
__global__ __launch_bounds__(256, 2) void gemm_pipe(
    const float* __restrict__ X,
    const float* __restrict__ W0, const float* __restrict__ W1,
    const float* __restrict__ W2,
    const float* __restrict__ b0p, const float* __restrict__ b1p,
    const float* __restrict__ b2p,
    float* __restrict__ Y0, float* __restrict__ Y1, float* __restrict__ Y2)
{
    extern __shared__ uint32_t smp[];
    const float* W    = blockIdx.z == 0 ? W0  : blockIdx.z == 1 ? W1  : W2;
    const float* bias = blockIdx.z == 0 ? b0p : blockIdx.z == 1 ? b1p : b2p;
    float* Y          = blockIdx.z == 0 ? Y0  : blockIdx.z == 1 ? Y1  : Y2;

    const int tid  = threadIdx.x;
    const int warp = tid >> 5;
    const int lane = tid & 31;
    const int gid  = lane >> 2;
    const int tig  = lane & 3;

    const int m0 = blockIdx.x * 128;
    const int n0 = blockIdx.y * 128;
    const int wm0 = (warp & 1) * 64;
    const int wn0 = (warp >> 1) * 32;

    const int lr  = tid >> 3;         // 0..31
    const int lc4 = (tid & 7) * 4;    // 0..28

    const uint32_t smem_base = (uint32_t)__cvta_generic_to_shared(smp);

    float acc[4][4][4];
#pragma unroll
    for (int mt = 0; mt < 4; mt++)
#pragma unroll
        for (int nt = 0; nt < 4; nt++)
#pragma unroll
            for (int i = 0; i < 4; i++) acc[mt][nt][i] = 0.0f;

    auto issue = [&](int k0, int buf) {
        uint32_t xb = smem_base + (uint32_t)buf * 8192u * 4u;
        uint32_t wb = xb + 4096u * 4u;
#pragma unroll
        for (int it = 0; it < 4; it++) {
            int rr = lr + it * 32;
            uint32_t cb = (uint32_t)lc4 ^ ((rr & 7) << 2);
            cp16(xb + (rr * 32 + cb) * 4, &X[(size_t)(m0 + rr) * 512 + k0 + lc4]);
            cp16(wb + (rr * 32 + cb) * 4, &W[(size_t)(n0 + rr) * 512 + k0 + lc4]);
        }
        asm volatile("cp.async.commit_group;" ::: "memory");
    };

    issue(0, 0);
    issue(32, 1);

    for (int i = 0; i < 16; i++) {
        if (i < 15) { asm volatile("cp.async.wait_group 1;" ::: "memory"); }
        else        { asm volatile("cp.async.wait_group 0;" ::: "memory"); }
        __syncthreads();

        const uint32_t* Xs = smp + (i & 1) * 8192;
        const uint32_t* Ws = Xs + 4096;

#pragma unroll
        for (int kk = 0; kk < 32; kk += 8) {
            uint32_t af[4][4], bf[4][2];
#pragma unroll
            for (int mt = 0; mt < 4; mt++) {
                int ra = wm0 + mt * 16 + gid;
                uint32_t sw = (ra & 7) << 2;
                uint32_t c0 = (uint32_t)(kk + tig) ^ sw;
                uint32_t c1 = (uint32_t)(kk + tig + 4) ^ sw;
                af[mt][0] = Xs[ra * 32 + c0];
                af[mt][1] = Xs[(ra + 8) * 32 + c0];
                af[mt][2] = Xs[ra * 32 + c1];
                af[mt][3] = Xs[(ra + 8) * 32 + c1];
            }
#pragma unroll
            for (int nt = 0; nt < 4; nt++) {
                int rb = wn0 + nt * 8 + gid;
                uint32_t sw = (rb & 7) << 2;
                bf[nt][0] = Ws[rb * 32 + ((uint32_t)(kk + tig) ^ sw)];
                bf[nt][1] = Ws[rb * 32 + ((uint32_t)(kk + tig + 4) ^ sw)];
            }
#pragma unroll
            for (int mt = 0; mt < 4; mt++)
#pragma unroll
                for (int nt = 0; nt < 4; nt++)
                    mma_tf32(acc[mt][nt], af[mt], bf[nt][0], bf[nt][1]);
        }
        __syncthreads();
        if (i < 14) issue((i + 2) * 32, i & 1);
    }

#pragma unroll
    for (int mt = 0; mt < 4; mt++) {
        int mr = m0 + wm0 + mt * 16 + gid;
#pragma unroll
        for (int nt = 0; nt < 4; nt++) {
            int nc = n0 + wn0 + nt * 8 + tig * 2;
            float2 b2 = *(const float2*)&bias[nc];
            float2 r0 = { acc[mt][nt][0] + b2.x, acc[mt][nt][1] + b2.y };
            *(float2*)&Y[(size_t)mr * 512 + nc] = r0;
            float2 r1 = { acc[mt][nt][2] + b2.x, acc[mt][nt][3] + b2.y };
            *(float2*)&Y[(size_t)(mr + 8) * 512 + nc] = r1;
        }
    }
}

// ---------------------------------------------------------------------------
// fp16 2-term flash attention: S = q . khi (exact via qhi+qlo), O = P . vhi
// (exact via Phi+Plo). Only hi-halves of K/V live in smem -> crossbar bytes
// and mma count halve vs 3-term. Output written pre-rounded to tf32 for the
// final GEMM. grid = (A/128, B*NHEAD), 8 warps x 16 q-rows.
// ---------------------------------------------------------------------------
#define KP 36
#define VP 72

__global__ __launch_bounds__(256, 2) void attn_mma(
    const float* __restrict__ Q,
    const float* __restrict__ K,
    const float* __restrict__ V,
    const float* __restrict__ rbias,
    float* __restrict__ O)
{
    __shared__ uint32_t Khi[64 * KP];
    __shared__ uint32_t Vph[32 * VP];

    const int tid  = threadIdx.x;
    const int warp = tid >> 5;
    const int lane = tid & 31;
    const int gid  = lane >> 2;
    const int tig  = lane & 3;

    const int pair = blockIdx.y;
    const int b = pair >> 3;
    const int h = pair & 7;
    const int q0 = blockIdx.x * 128;
    const int wm = warp * 16;
    const float scale = 0.125f;

    // Q fragments in registers (full precision via hi+lo)
    uint32_t qhi[4][4], qlo[4][4];
    {
        const int r0g = q0 + wm + gid;
        const size_t base0 = (size_t)(r0g * B_DIM + b) * DMODEL + h * HEAD_DIM;
        const size_t base1 = base0 + (size_t)8 * B_DIM * DMODEL;
#pragma unroll
        for (int kt = 0; kt < 4; kt++) {
            int c0 = kt * 16 + 2 * tig;
            float2 x0 = *(const float2*)&Q[base0 + c0];
            float2 x1 = *(const float2*)&Q[base1 + c0];
            float2 x2 = *(const float2*)&Q[base0 + c0 + 8];
            float2 x3 = *(const float2*)&Q[base1 + c0 + 8];
            split_h2(x0.x, x0.y, qhi[kt][0], qlo[kt][0]);
            split_h2(x1.x, x1.y, qhi[kt][1], qlo[kt][1]);
            split_h2(x2.x, x2.y, qhi[kt][2], qlo[kt][2]);
            split_h2(x3.x, x3.y, qhi[kt][3], qlo[kt][3]);
        }
    }

    float o[8][4];
#pragma unroll
    for (int nt = 0; nt < 8; nt++)
#pragma unroll
        for (int i = 0; i < 4; i++) o[nt][i] = 0.0f;
    float m0r = -1e30f, m1r = -1e30f, l0r = 0.0f, l1r = 0.0f;

    const int f4c = (tid & 15) * 4;
    const int rld = tid >> 4;

    for (int kb = 0; kb < A_DIM; kb += 64) {
        // ---- cooperative K / V load (hi halves only) ----
#pragma unroll
        for (int it = 0; it < 4; it++) {
            int r = rld + it * 16;
            size_t gb = (size_t)((kb + r) * B_DIM + b) * DMODEL + h * HEAD_DIM + f4c;
            float4 kv4 = *(const float4*)&K[gb];
            uint2 kh;
            kh.x = pack_h2(kv4.x, kv4.y);
            kh.y = pack_h2(kv4.z, kv4.w);
            *(uint2*)&Khi[r * KP + (f4c >> 1)] = kh;

            float4 vv = *(const float4*)&V[gb];
            int hidx = ((r >> 1) * VP + f4c) * 2 + (r & 1);
            float vf[4] = { vv.x, vv.y, vv.z, vv.w };
#pragma unroll
            for (int j = 0; j < 4; j++)
                ((__half*)Vph)[hidx + 2 * j] = __float2half_rn(vf[j]);
        }
        __syncthreads();

        // ---- S = Q K^T (2 mma per frag) ----
        float s[8][4];
#pragma unroll
        for (int nt = 0; nt < 8; nt++)
#pragma unroll
            for (int i = 0; i < 4; i++) s[nt][i] = 0.0f;

#pragma unroll
        for (int kt = 0; kt < 4; kt++) {
#pragma unroll
            for (int nt = 0; nt < 8; nt++) {
                int wb = (nt * 8 + gid) * KP + kt * 8 + tig;
                uint32_t bh0 = Khi[wb], bh1 = Khi[wb + 4];
                mma_f16(s[nt], qhi[kt], bh0, bh1);
                mma_f16(s[nt], qlo[kt], bh0, bh1);
            }
        }

        // ---- scale + relation bias ----
        {
            const float* br0 = &rbias[(size_t)(q0 + wm + gid) * A_DIM + kb];
            const float* br1 = br0 + 8 * A_DIM;
#pragma unroll
            for (int nt = 0; nt < 8; nt++) {
                float2 b0 = *(const float2*)&br0[nt * 8 + 2 * tig];
                float2 b1 = *(const float2*)&br1[nt * 8 + 2 * tig];
                s[nt][0] = s[nt][0] * scale + b0.x;
                s[nt][1] = s[nt][1] * scale + b0.y;
                s[nt][2] = s[nt][2] * scale + b1.x;
                s[nt][3] = s[nt][3] * scale + b1.y;
            }
        }

        // ---- online softmax ----
        {
            float mx0 = -1e30f, mx1 = -1e30f;
#pragma unroll
            for (int nt = 0; nt < 8; nt++) {
                mx0 = fmaxf(mx0, fmaxf(s[nt][0], s[nt][1]));
                mx1 = fmaxf(mx1, fmaxf(s[nt][2], s[nt][3]));
            }
            mx0 = fmaxf(mx0, __shfl_xor_sync(0xffffffffu, mx0, 1));
            mx0 = fmaxf(mx0, __shfl_xor_sync(0xffffffffu, mx0, 2));
            mx1 = fmaxf(mx1, __shfl_xor_sync(0xffffffffu, mx1, 1));
            mx1 = fmaxf(mx1, __shfl_xor_sync(0xffffffffu, mx1, 2));

            float mn0 = fmaxf(m0r, mx0);
            float mn1 = fmaxf(m1r, mx1);
            float c0 = __expf(m0r - mn0);
            float c1 = __expf(m1r - mn1);
            m0r = mn0; m1r = mn1;

            float rs0 = 0.0f, rs1 = 0.0f;
#pragma unroll
            for (int nt = 0; nt < 8; nt++) {
                s[nt][0] = __expf(s[nt][0] - mn0);
                s[nt][1] = __expf(s[nt][1] - mn0);
                s[nt][2] = __expf(s[nt][2] - mn1);
                s[nt][3] = __expf(s[nt][3] - mn1);
                rs0 += s[nt][0] + s[nt][1];
                rs1 += s[nt][2] + s[nt][3];
            }
            rs0 += __shfl_xor_sync(0xffffffffu, rs0, 1);
            rs0 += __shfl_xor_sync(0xffffffffu, rs0, 2);
            rs1 += __shfl_xor_sync(0xffffffffu, rs1, 1);
            rs1 += __shfl_xor_sync(0xffffffffu, rs1, 2);

            l0r = l0r * c0 + rs0;
            l1r = l1r * c1 + rs1;
#pragma unroll
            for (int nt = 0; nt < 8; nt++) {
                o[nt][0] *= c0; o[nt][1] *= c0;
                o[nt][2] *= c1; o[nt][3] *= c1;
            }
        }

        // ---- O += P V (P hi+lo from registers, V hi only) ----
#pragma unroll
        for (int j = 0; j < 4; j++) {
            uint32_t ah[4], al[4];
            split_h2(s[2*j][0],   s[2*j][1],   ah[0], al[0]);
            split_h2(s[2*j][2],   s[2*j][3],   ah[1], al[1]);
            split_h2(s[2*j+1][0], s[2*j+1][1], ah[2], al[2]);
            split_h2(s[2*j+1][2], s[2*j+1][3], ah[3], al[3]);
#pragma unroll
            for (int nt = 0; nt < 8; nt++) {
                int wb = (j * 8 + tig) * VP + nt * 8 + gid;
                uint32_t bh0 = Vph[wb], bh1 = Vph[wb + 4 * VP];
                mma_f16(o[nt], ah, bh0, bh1);
                mma_f16(o[nt], al, bh0, bh1);
            }
        }
        __syncthreads();
    }

    // ---- normalize + write (tf32-rounded for final GEMM) ----
    {
        float i0 = 1.0f / l0r, i1 = 1.0f / l1r;
        const int r0g = q0 + wm + gid;
        size_t base0 = (size_t)(r0g * B_DIM + b) * DMODEL + h * HEAD_DIM;
        size_t base1 = base0 + (size_t)8 * B_DIM * DMODEL;
#pragma unroll
        for (int nt = 0; nt < 8; nt++) {
            int c = nt * 8 + 2 * tig;
            float2 r0 = { __uint_as_float(f2tf32(o[nt][0] * i0)),
                          __uint_as_float(f2tf32(o[nt][1] * i0)) };
            float2 r1 = { __uint_as_float(f2tf32(o[nt][2] * i1)),
                          __uint_as_float(f2tf32(o[nt][3] * i1)) };
            *(float2*)&O[base0 + c] = r0;
            *(float2*)&O[base1 + c] = r1;
        }
    }
}

// ---------------------------------------------------------------------------

extern "C" void kernel_launch(void* const* d_in, const int* in_sizes, int n_in,
                              void* d_out, int out_size)
{
    const float* src   = (const float*)d_in[0];
    const float* rbias = (const float*)d_in[1];
    const float* Wq    = (const float*)d_in[2];
    const float* bq    = (const float*)d_in[3];
    const float* Wk    = (const float*)d_in[4];
    const float* bk    = (const float*)d_in[5];
    const float* Wv    = (const float*)d_in[6];
    const float* bv    = (const float*)d_in[7];
    const float* Wo    = (const float*)d_in[8];
    const float* bo    = (const float*)d_in[9];
    float* out = (float*)d_out;

    float *gq, *gk, *gv, *ga, *gx, *gwq, *gwk, *gwv, *gwo;
    cudaGetSymbolAddress((void**)&gq, g_q);
    cudaGetSymbolAddress((void**)&gk, g_k);
    cudaGetSymbolAddress((void**)&gv, g_v);
    cudaGetSymbolAddress((void**)&ga, g_attn);
    cudaGetSymbolAddress((void**)&gx, g_x32);
    cudaGetSymbolAddress((void**)&gwq, g_wq32);
    cudaGetSymbolAddress((void**)&gwk, g_wk32);
    cudaGetSymbolAddress((void**)&gwv, g_wv32);
    cudaGetSymbolAddress((void**)&gwo, g_wo32);

    cudaFuncSetAttribute(gemm_pipe, cudaFuncAttributeMaxDynamicSharedMemorySize,
                         65536);

    // 1) pre-round inputs to tf32
    tf32_round_all<<<(NX4 + 4 * NW4 + 255) / 256, 256>>>(
        (const float4*)src, (const float4*)Wq, (const float4*)Wk,
        (const float4*)Wv, (const float4*)Wo,
        (float4*)gx, (float4*)gwq, (float4*)gwk, (float4*)gwv, (float4*)gwo);

    // 2) fused QKV projection
    gemm_pipe<<<dim3(128, 4, 3), 256, 65536>>>(
        gx, gwq, gwk, gwv, bq, bk, bv, gq, gk, gv);

    // 3) attention
    dim3 agrid(A_DIM / 128, B_DIM * NHEAD);
    attn_mma<<<agrid, 256>>>(gq, gk, gv, rbias, ga);

    // 4) output projection
    gemm_pipe<<<dim3(128, 4, 1), 256, 65536>>>(
        ga, gwo, gwo, gwo, bo, bo, bo, out, out, out);
}